// round 12
// baseline (speedup 1.0000x reference)
#include <cuda_runtime.h>
#include <cuda_bf16.h>
#include <cstdint>

#define BB 32
#define CC 5
#define HH 50
#define SS 20
#define EE 300
#define EP 320               // padded E (zeros in 300..319)
#define KK 20
#define F4N 75
#define NCS 100
#define THREADS 224
#define NGRP2 50             // 2-row groups
#define NROWS_CDD (BB * CC * SS)     // 3200
#define NROWS_HIS (BB * HH * SS)     // 32000
#define NROWS_ALL (NROWS_CDD + NROWS_HIS)

#define NC_STD  (-72.134752f)
#define NC_LAST (-721347.52f)

struct Smem {
    float hisT[EP * SS];        // 25600B, e-major [e][t], pad e>=300 zeroed
    float simbuf[NCS * SS];     // 8000B
    float padh[SS];
    float padc[NCS];
    float wv[KK];
    float cont[THREADS];
};

__device__ float g_cddN[NROWS_CDD * EP];   // normalized + zero-padded to EP
__device__ float g_hisN[NROWS_HIS * EE];
__device__ float g_partial[BB * HH * CC];
__device__ unsigned int g_done;

__device__ __forceinline__ float ex2_approx(float x) {
    float r;
    asm("ex2.approx.ftz.f32 %0, %1;" : "=f"(r) : "f"(x));
    return r;
}
__device__ __forceinline__ void fma2(unsigned long long& acc,
                                     unsigned long long a, unsigned long long b) {
    asm("fma.rn.f32x2 %0, %1, %2, %0;" : "+l"(acc) : "l"(a), "l"(b));
}
__device__ __forceinline__ unsigned long long dupf(float x) {
    unsigned long long r;
    asm("mov.b64 %0, {%1, %1};" : "=l"(r) : "f"(x));
    return r;
}

// ---------------- prep: L2-normalize embedding rows into dense scratch ----------------
__global__ __launch_bounds__(256)
void knrm_prep(const int* __restrict__ cand, const int* __restrict__ clk,
               const float* __restrict__ emb)
{
    const int wid = threadIdx.x >> 5, lane = threadIdx.x & 31;
    const int row = blockIdx.x * 8 + wid;
    if (row >= NROWS_ALL) return;
    const bool isCdd = (row < NROWS_CDD);
    int tok;
    float* dst;
    if (isCdd) { tok = cand[row];             dst = g_cddN + (size_t)row * EP; }
    else       { tok = clk[row - NROWS_CDD];  dst = g_hisN + (size_t)(row - NROWS_CDD) * EE; }
    const float* src = emb + (size_t)tok * EE;

    float4 v[3];
    float ss = 0.f;
    #pragma unroll
    for (int i = 0; i < 3; ++i) {
        int f = lane + i * 32;
        if (f < F4N) {
            v[i] = *reinterpret_cast<const float4*>(src + f * 4);
            ss = fmaf(v[i].x, v[i].x, ss);
            ss = fmaf(v[i].y, v[i].y, ss);
            ss = fmaf(v[i].z, v[i].z, ss);
            ss = fmaf(v[i].w, v[i].w, ss);
        }
    }
    #pragma unroll
    for (int o = 16; o; o >>= 1) ss += __shfl_xor_sync(0xffffffffu, ss, o);
    float inv = 1.0f / fmaxf(sqrtf(ss), 1e-12f);
    #pragma unroll
    for (int i = 0; i < 3; ++i) {
        int f = lane + i * 32;
        if (f < F4N) {
            float4 o4 = make_float4(v[i].x * inv, v[i].y * inv, v[i].z * inv, v[i].w * inv);
            *reinterpret_cast<float4*>(dst + f * 4) = o4;
        } else if (isCdd && f < EP / 4) {
            *reinterpret_cast<float4*>(dst + f * 4) = make_float4(0.f, 0.f, 0.f, 0.f);
        }
    }
}

__global__ __launch_bounds__(THREADS, 3)
void knrm_main(const float* __restrict__ cpad, const float* __restrict__ hpad,
               const float* __restrict__ ltr_w, const float* __restrict__ ltr_b,
               float* __restrict__ out)
{
    extern __shared__ float smraw[];
    Smem* sm = reinterpret_cast<Smem*>(smraw);
    const int tid = threadIdx.x;
    const int wid = tid >> 5, lane = tid & 31;
    const int b = blockIdx.x / HH;
    const int h = blockIdx.x % HH;

    const int ec = lane >> 3;            // 0..3
    const int g  = lane & 7;
    const int grp = wid * 8 + g;         // 0..55, active < 50
    const int grpC = (grp < NGRP2) ? grp : (NGRP2 - 1);

    unsigned long long acc[2][10];
    #pragma unroll
    for (int r = 0; r < 2; ++r)
        #pragma unroll
        for (int p = 0; p < 10; ++p) acc[r][p] = 0ull;

    const float* hisSrc = g_hisN + (size_t)(b * HH + h) * SS * EE;
    const float* cddSrc = g_cddN + (size_t)b * NCS * EP;

    // -------- preamble: hisT (transposed) + zero pad + small tables --------
    for (int i = tid; i < SS * F4N; i += THREADS) {
        int t = i / F4N, f = i % F4N;
        float4 v = *reinterpret_cast<const float4*>(hisSrc + t * EE + f * 4);
        sm->hisT[(f * 4 + 0) * SS + t] = v.x;
        sm->hisT[(f * 4 + 1) * SS + t] = v.y;
        sm->hisT[(f * 4 + 2) * SS + t] = v.z;
        sm->hisT[(f * 4 + 3) * SS + t] = v.w;
    }
    for (int i = tid; i < (EP - EE) * SS; i += THREADS)
        sm->hisT[EE * SS + i] = 0.f;
    if (tid < SS)  sm->padh[tid] = hpad[(b * HH + h) * SS + tid];
    if (tid < KK)  sm->wv[tid]   = ltr_w[h * KK + tid];
    for (int i = tid; i < NCS; i += THREADS) sm->padc[i] = cpad[b * NCS + i];
    __syncthreads();

    // -------- phase A: straight-line, cdd from global, hisT from smem --------
    {
        const float4* c0 = reinterpret_cast<const float4*>(cddSrc + (size_t)(grpC * 2) * EP) + ec;
        const float4* c1 = reinterpret_cast<const float4*>(cddSrc + (size_t)(grpC * 2 + 1) * EP) + ec;
        const float* hbase = sm->hisT + ec * 4 * SS;
        #pragma unroll 5
        for (int i = 0; i < 20; ++i) {
            float4 a0 = __ldg(c0 + i * 4);
            float4 a1 = __ldg(c1 + i * 4);
            const float* hb = hbase + i * (16 * SS);
            #pragma unroll
            for (int j = 0; j < 4; ++j) {
                float v0 = (j == 0) ? a0.x : (j == 1) ? a0.y : (j == 2) ? a0.z : a0.w;
                float v1 = (j == 0) ? a1.x : (j == 1) ? a1.y : (j == 2) ? a1.z : a1.w;
                unsigned long long d0 = dupf(v0), d1 = dupf(v1);
                const ulonglong2* hp = reinterpret_cast<const ulonglong2*>(hb + j * SS);
                #pragma unroll
                for (int q = 0; q < 5; ++q) {
                    ulonglong2 hv = hp[q];
                    fma2(acc[0][q * 2 + 0], d0, hv.x);
                    fma2(acc[0][q * 2 + 1], d0, hv.y);
                    fma2(acc[1][q * 2 + 0], d1, hv.x);
                    fma2(acc[1][q * 2 + 1], d1, hv.y);
                }
            }
        }
    }

    // -------- reduce over ec (16, 8 -> lanes 0..7) --------
    #pragma unroll
    for (int o = 16; o >= 8; o >>= 1) {
        #pragma unroll
        for (int r = 0; r < 2; ++r)
            #pragma unroll
            for (int p = 0; p < 10; ++p) {
                unsigned long long other = __shfl_down_sync(0xffffffffu, acc[r][p], o);
                float2 a = *reinterpret_cast<float2*>(&acc[r][p]);
                float2 bo = *reinterpret_cast<float2*>(&other);
                a.x += bo.x; a.y += bo.y;
                acc[r][p] = *reinterpret_cast<unsigned long long*>(&a);
            }
    }
    if (lane < 8 && grp < NGRP2) {
        int r0 = grp * 2;
        #pragma unroll
        for (int r = 0; r < 2; ++r) {
            #pragma unroll
            for (int p = 0; p < 10; ++p) {
                float2 a = *reinterpret_cast<float2*>(&acc[r][p]);
                int t0 = p * 2;
                sm->simbuf[(r0 + r) * SS + t0 + 0] = a.x;
                sm->simbuf[(r0 + r) * SS + t0 + 1] = a.y;
            }
        }
    }
    __syncthreads();

    // -------- phase B --------
    float contrib = 0.0f;
    if (tid < 200) {
        int cs = tid >> 1, kh = tid & 1;
        float ps[10];
        #pragma unroll
        for (int k = 0; k < 10; ++k) ps[k] = 0.f;
        for (int t = 0; t < SS; ++t) {
            float s  = sm->simbuf[cs * SS + t];
            float pt = sm->padh[t];
            #pragma unroll
            for (int k = 0; k < 10; ++k) {
                int kk = kh * 10 + k;
                float mu = -0.9f + 0.1f * (float)kk;
                float nc = (kh == 1 && k == 9) ? NC_LAST : NC_STD;
                float d = s - mu;
                ps[k] = fmaf(pt, ex2_approx(d * d * nc), ps[k]);
            }
        }
        float accw = 0.f;
        #pragma unroll
        for (int k = 0; k < 10; ++k) {
            float lp = __logf(fmaxf(ps[k], 1e-10f));
            accw = fmaf(lp, sm->wv[kh * 10 + k], accw);
        }
        contrib = accw * 0.01f * sm->padc[cs];
    }
    sm->cont[tid] = contrib;
    __syncthreads();

    if (tid < CC) {
        float s = 0.f;
        #pragma unroll 8
        for (int i = 0; i < 40; ++i) s += sm->cont[tid * 40 + i];
        g_partial[(b * HH + h) * CC + tid] = s;
    }
    __syncthreads();

    // -------- fused finalize --------
    __shared__ unsigned int isLast;
    if (tid == 0) {
        __threadfence();
        unsigned int v = atomicAdd(&g_done, 1u);
        isLast = (v == (unsigned)(BB * HH - 1)) ? 1u : 0u;
    }
    __syncthreads();
    if (isLast) {
        if (tid == 0) { g_done = 0; __threadfence(); }
        float* sc = sm->cont;
        if (tid < BB * CC) {
            int bb2 = tid / CC, c = tid % CC;
            float s = ltr_b[0];
            for (int hh = 0; hh < HH; ++hh)
                s += g_partial[(bb2 * HH + hh) * CC + c];
            sc[tid] = s;
        }
        __syncthreads();
        if (tid < BB * CC) {
            int bb2 = tid / CC;
            float m = -1e30f;
            #pragma unroll
            for (int c2 = 0; c2 < CC; ++c2) m = fmaxf(m, sc[bb2 * CC + c2]);
            float se = 0.f;
            #pragma unroll
            for (int c2 = 0; c2 < CC; ++c2) se += expf(sc[bb2 * CC + c2] - m);
            out[tid] = sc[tid] - m - logf(se);
        }
    }
}

extern "C" void kernel_launch(void* const* d_in, const int* in_sizes, int n_in,
                              void* d_out, int out_size)
{
    const int*   cand = (const int*)  d_in[0];
    const int*   clk  = (const int*)  d_in[1];
    const float* cpad = (const float*)d_in[2];
    const float* hpad = (const float*)d_in[3];
    const float* emb  = (const float*)d_in[4];
    const float* w    = (const float*)d_in[5];
    const float* bb   = (const float*)d_in[6];

    size_t smem = sizeof(Smem);
    cudaFuncSetAttribute(knrm_main, cudaFuncAttributeMaxDynamicSharedMemorySize, (int)smem);

    knrm_prep<<<(NROWS_ALL + 7) / 8, 256>>>(cand, clk, emb);
    knrm_main<<<BB * HH, THREADS, smem>>>(cpad, hpad, w, bb, (float*)d_out);
}

// round 14
// speedup vs baseline: 1.4203x; 1.4203x over previous
#include <cuda_runtime.h>
#include <cuda_bf16.h>
#include <cstdint>

#define BB 32
#define CC 5
#define HH 50
#define SS 20
#define EE 300
#define EPC 320              // padded K (zeros 300..319)
#define KK 20
#define F4N 75
#define NCS 100
#define THREADS 128
#define NROWS_CDD (BB * CC * SS)     // 3200
#define NROWS_HIS (BB * HH * SS)     // 32000
#define NROWS_ALL (NROWS_CDD + NROWS_HIS)
#define NCHUNK 5             // K chunks of 64 bf16
#define ASTR 144             // smem row stride bytes (64 bf16 = 128B + 16B pad)
#define SIMSTR 26            // simbuf row stride (floats)

#define NC_STD  (-72.134752f)
#define NC_LAST (-721347.52f)

// smem offsets (bytes)
#define SM_AHI 0
#define SM_ALO (SM_AHI + 128 * ASTR)        // 18432
#define SM_BHI (SM_ALO + 128 * ASTR)        // 36864
#define SM_BLO (SM_BHI + 24 * ASTR)         // 40320
#define SM_SIM (SM_BLO + 24 * ASTR)         // 43776
#define SM_PADH (SM_SIM + 128 * SIMSTR * 4) // 57088
#define SM_PADC (SM_PADH + 128)
#define SM_WV   (SM_PADC + countof_padc)
#define countof_padc 416
#define SM_CONT (SM_WV + 96)
#define SM_FSC  (SM_CONT + 512)
#define SM_TOTAL (SM_FSC + 704)

static __device__ __forceinline__ uint32_t smem_u32(const void* p) {
    uint32_t a;
    asm("{ .reg .u64 t; cvta.to.shared.u64 t, %1; cvt.u32.u64 %0, t; }" : "=r"(a) : "l"(p));
    return a;
}
static __device__ __forceinline__ void ldsm_x4(uint32_t (&r)[4], uint32_t addr) {
    asm volatile("ldmatrix.sync.aligned.m8n8.x4.shared.b16 {%0,%1,%2,%3}, [%4];"
        : "=r"(r[0]), "=r"(r[1]), "=r"(r[2]), "=r"(r[3]) : "r"(addr));
}
static __device__ __forceinline__ void ldsm_x2(uint32_t (&r)[2], uint32_t addr) {
    asm volatile("ldmatrix.sync.aligned.m8n8.x2.shared.b16 {%0,%1}, [%2];"
        : "=r"(r[0]), "=r"(r[1]) : "r"(addr));
}
static __device__ __forceinline__ void mma16816(float (&d)[4], const uint32_t (&a)[4],
                                                const uint32_t (&b)[2]) {
    asm volatile("mma.sync.aligned.m16n8k16.row.col.f32.bf16.bf16.f32 "
        "{%0,%1,%2,%3}, {%4,%5,%6,%7}, {%8,%9}, {%0,%1,%2,%3};"
        : "+f"(d[0]), "+f"(d[1]), "+f"(d[2]), "+f"(d[3])
        : "r"(a[0]), "r"(a[1]), "r"(a[2]), "r"(a[3]), "r"(b[0]), "r"(b[1]));
}
__device__ __forceinline__ float ex2_approx(float x) {
    float r;
    asm("ex2.approx.ftz.f32 %0, %1;" : "=f"(r) : "f"(x));
    return r;
}

__device__ __align__(256) __nv_bfloat16 g_cddH[NROWS_CDD * EPC];
__device__ __align__(256) __nv_bfloat16 g_cddL[NROWS_CDD * EPC];
__device__ __align__(256) __nv_bfloat16 g_hisH[NROWS_HIS * EPC];
__device__ __align__(256) __nv_bfloat16 g_hisL[NROWS_HIS * EPC];
__device__ float g_partial[BB * HH * CC];
__device__ unsigned int g_done;

// ---------------- prep: normalize rows, split to bf16 hi/lo, pad K to 320 ----------------
__global__ __launch_bounds__(256)
void knrm_prep(const int* __restrict__ cand, const int* __restrict__ clk,
               const float* __restrict__ emb)
{
    const int wid = threadIdx.x >> 5, lane = threadIdx.x & 31;
    const int row = blockIdx.x * 8 + wid;
    if (row >= NROWS_ALL) return;
    const bool isCdd = (row < NROWS_CDD);
    int tok;
    __nv_bfloat16 *dH, *dL;
    if (isCdd) { tok = cand[row];
        dH = g_cddH + (size_t)row * EPC; dL = g_cddL + (size_t)row * EPC; }
    else { tok = clk[row - NROWS_CDD];
        dH = g_hisH + (size_t)(row - NROWS_CDD) * EPC; dL = g_hisL + (size_t)(row - NROWS_CDD) * EPC; }
    const float* src = emb + (size_t)tok * EE;

    float4 v[3];
    float ss = 0.f;
    #pragma unroll
    for (int i = 0; i < 3; ++i) {
        int f = lane + i * 32;
        if (f < F4N) {
            v[i] = *reinterpret_cast<const float4*>(src + f * 4);
            ss = fmaf(v[i].x, v[i].x, ss);
            ss = fmaf(v[i].y, v[i].y, ss);
            ss = fmaf(v[i].z, v[i].z, ss);
            ss = fmaf(v[i].w, v[i].w, ss);
        }
    }
    #pragma unroll
    for (int o = 16; o; o >>= 1) ss += __shfl_xor_sync(0xffffffffu, ss, o);
    float inv = 1.0f / fmaxf(sqrtf(ss), 1e-12f);
    #pragma unroll
    for (int i = 0; i < 3; ++i) {
        int f = lane + i * 32;
        if (f < EPC / 4) {
            float x0 = 0.f, x1 = 0.f, x2 = 0.f, x3 = 0.f;
            if (f < F4N) { x0 = v[i].x * inv; x1 = v[i].y * inv; x2 = v[i].z * inv; x3 = v[i].w * inv; }
            __nv_bfloat16 h0 = __float2bfloat16(x0), h1 = __float2bfloat16(x1);
            __nv_bfloat16 h2 = __float2bfloat16(x2), h3 = __float2bfloat16(x3);
            __nv_bfloat16 l0 = __float2bfloat16(x0 - __bfloat162float(h0));
            __nv_bfloat16 l1 = __float2bfloat16(x1 - __bfloat162float(h1));
            __nv_bfloat16 l2 = __float2bfloat16(x2 - __bfloat162float(h2));
            __nv_bfloat16 l3 = __float2bfloat16(x3 - __bfloat162float(h3));
            __nv_bfloat16 hp[4] = {h0, h1, h2, h3};
            __nv_bfloat16 lp[4] = {l0, l1, l2, l3};
            *reinterpret_cast<uint2*>(dH + f * 4) = *reinterpret_cast<uint2*>(hp);
            *reinterpret_cast<uint2*>(dL + f * 4) = *reinterpret_cast<uint2*>(lp);
        }
    }
}

// ---------------- main: mma.sync bf16 2-split GEMM + KNRM pooling ----------------
__global__ __launch_bounds__(THREADS, 3)
void knrm_main(const float* __restrict__ cpad, const float* __restrict__ hpad,
               const float* __restrict__ ltr_w, const float* __restrict__ ltr_b,
               float* __restrict__ out)
{
    extern __shared__ char smem[];
    const uint32_t sb = smem_u32(smem);
    const int tid = threadIdx.x;
    const int wid = tid >> 5, lane = tid & 31;
    const int b = blockIdx.x / HH;
    const int h = blockIdx.x % HH;

    float* simS  = reinterpret_cast<float*>(smem + SM_SIM);
    float* padhS = reinterpret_cast<float*>(smem + SM_PADH);
    float* padcS = reinterpret_cast<float*>(smem + SM_PADC);
    float* wvS   = reinterpret_cast<float*>(smem + SM_WV);
    float* contS = reinterpret_cast<float*>(smem + SM_CONT);
    float* fscS  = reinterpret_cast<float*>(smem + SM_FSC);

    if (tid < SS)  padhS[tid] = hpad[(b * HH + h) * SS + tid];
    if (tid < KK)  wvS[tid]   = ltr_w[h * KK + tid];
    if (tid < NCS) padcS[tid] = cpad[b * NCS + tid];

    const char* cH = reinterpret_cast<const char*>(g_cddH) + (size_t)b * NCS * EPC * 2;
    const char* cL = reinterpret_cast<const char*>(g_cddL) + (size_t)b * NCS * EPC * 2;
    const char* hH = reinterpret_cast<const char*>(g_hisH) + (size_t)(b * HH + h) * SS * EPC * 2;
    const char* hL = reinterpret_cast<const char*>(g_hisL) + (size_t)(b * HH + h) * SS * EPC * 2;

    float d[2][3][4];
    #pragma unroll
    for (int mi = 0; mi < 2; ++mi)
        #pragma unroll
        for (int ni = 0; ni < 3; ++ni)
            #pragma unroll
            for (int q = 0; q < 4; ++q) d[mi][ni][q] = 0.f;

    // per-lane ldmatrix base addresses
    const uint32_t aBaseH = sb + SM_AHI + (wid * 32 + (lane & 15)) * ASTR + (lane >> 4) * 16;
    const uint32_t aBaseL = aBaseH + (SM_ALO - SM_AHI);
    const uint32_t bBaseH = sb + SM_BHI + (lane & 7) * ASTR + ((lane >> 3) & 1) * 16;
    const uint32_t bBaseL = bBaseH + (SM_BLO - SM_BHI);

    for (int c = 0; c < NCHUNK; ++c) {
        // load A rows 0..99 (both splits), 64 bf16 = 128B per row
        for (int i = tid; i < NCS * 8; i += THREADS) {
            int r = i >> 3, q = i & 7;
            uint32_t dst = r * ASTR + q * 16;
            size_t src = (size_t)r * (EPC * 2) + c * 128 + q * 16;
            *reinterpret_cast<uint4*>(smem + SM_AHI + dst) = *reinterpret_cast<const uint4*>(cH + src);
            *reinterpret_cast<uint4*>(smem + SM_ALO + dst) = *reinterpret_cast<const uint4*>(cL + src);
        }
        // load B rows 0..19 (both splits)
        for (int i = tid; i < SS * 8; i += THREADS) {
            int r = i >> 3, q = i & 7;
            uint32_t dst = r * ASTR + q * 16;
            size_t src = (size_t)r * (EPC * 2) + c * 128 + q * 16;
            *reinterpret_cast<uint4*>(smem + SM_BHI + dst) = *reinterpret_cast<const uint4*>(hH + src);
            *reinterpret_cast<uint4*>(smem + SM_BLO + dst) = *reinterpret_cast<const uint4*>(hL + src);
        }
        __syncthreads();

        #pragma unroll
        for (int ks = 0; ks < 4; ++ks) {
            uint32_t bh[3][2], bl[3][2];
            #pragma unroll
            for (int ni = 0; ni < 3; ++ni) {
                ldsm_x2(bh[ni], bBaseH + ni * (8 * ASTR) + ks * 32);
                ldsm_x2(bl[ni], bBaseL + ni * (8 * ASTR) + ks * 32);
            }
            #pragma unroll
            for (int mi = 0; mi < 2; ++mi) {
                uint32_t ah[4], al[4];
                ldsm_x4(ah, aBaseH + mi * (16 * ASTR) + ks * 32);
                ldsm_x4(al, aBaseL + mi * (16 * ASTR) + ks * 32);
                #pragma unroll
                for (int ni = 0; ni < 3; ++ni) {
                    mma16816(d[mi][ni], ah, bh[ni]);
                    mma16816(d[mi][ni], ah, bl[ni]);
                    mma16816(d[mi][ni], al, bh[ni]);
                }
            }
        }
        __syncthreads();
    }

    // store sim to smem: d0,d1 -> row m, cols 2(l&3)+8ni; d2,d3 -> row m+8
    #pragma unroll
    for (int mi = 0; mi < 2; ++mi)
        #pragma unroll
        for (int ni = 0; ni < 3; ++ni) {
            int row0 = wid * 32 + mi * 16 + (lane >> 2);
            int col = ni * 8 + (lane & 3) * 2;
            *reinterpret_cast<float2*>(&simS[row0 * SIMSTR + col]) =
                make_float2(d[mi][ni][0], d[mi][ni][1]);
            *reinterpret_cast<float2*>(&simS[(row0 + 8) * SIMSTR + col]) =
                make_float2(d[mi][ni][2], d[mi][ni][3]);
        }
    __syncthreads();

    // phase B: thread = row (cs), all 20 kernels
    float contrib = 0.0f;
    if (tid < NCS) {
        float ps[KK];
        #pragma unroll
        for (int k = 0; k < KK; ++k) ps[k] = 0.f;
        #pragma unroll 4
        for (int t = 0; t < SS; ++t) {
            float s = simS[tid * SIMSTR + t];
            float pt = padhS[t];
            #pragma unroll
            for (int k = 0; k < KK; ++k) {
                float mu = -0.9f + 0.1f * (float)k;
                float nc = (k == 19) ? NC_LAST : NC_STD;
                float dd = s - mu;
                ps[k] = fmaf(pt, ex2_approx(dd * dd * nc), ps[k]);
            }
        }
        float accw = 0.f;
        #pragma unroll
        for (int k = 0; k < KK; ++k) {
            float lp = __logf(fmaxf(ps[k], 1e-10f));
            accw = fmaf(lp, wvS[k], accw);
        }
        contrib = accw * 0.01f * padcS[tid];
    }
    contS[tid] = contrib;
    __syncthreads();

    if (tid < CC) {
        float s = 0.f;
        #pragma unroll
        for (int i = 0; i < SS; ++i) s += contS[tid * SS + i];
        g_partial[(b * HH + h) * CC + tid] = s;
    }
    __syncthreads();

    // fused finalize: last block does h-sum + log_softmax
    __shared__ unsigned int isLast;
    if (tid == 0) {
        __threadfence();
        unsigned int v = atomicAdd(&g_done, 1u);
        isLast = (v == (unsigned)(BB * HH - 1)) ? 1u : 0u;
    }
    __syncthreads();
    if (isLast) {
        if (tid == 0) { g_done = 0; __threadfence(); }
        for (int idx = tid; idx < BB * CC; idx += THREADS) {
            int bb2 = idx / CC, c = idx % CC;
            float s = ltr_b[0];
            for (int hh = 0; hh < HH; ++hh)
                s += g_partial[(bb2 * HH + hh) * CC + c];
            fscS[idx] = s;
        }
        __syncthreads();
        for (int idx = tid; idx < BB * CC; idx += THREADS) {
            int bb2 = idx / CC;
            float m = -1e30f;
            #pragma unroll
            for (int c2 = 0; c2 < CC; ++c2) m = fmaxf(m, fscS[bb2 * CC + c2]);
            float se = 0.f;
            #pragma unroll
            for (int c2 = 0; c2 < CC; ++c2) se += expf(fscS[bb2 * CC + c2] - m);
            out[idx] = fscS[idx] - m - logf(se);
        }
    }
}

extern "C" void kernel_launch(void* const* d_in, const int* in_sizes, int n_in,
                              void* d_out, int out_size)
{
    const int*   cand = (const int*)  d_in[0];
    const int*   clk  = (const int*)  d_in[1];
    const float* cpad = (const float*)d_in[2];
    const float* hpad = (const float*)d_in[3];
    const float* emb  = (const float*)d_in[4];
    const float* w    = (const float*)d_in[5];
    const float* bb   = (const float*)d_in[6];

    cudaFuncSetAttribute(knrm_main, cudaFuncAttributeMaxDynamicSharedMemorySize, SM_TOTAL);

    knrm_prep<<<(NROWS_ALL + 7) / 8, 256>>>(cand, clk, emb);
    knrm_main<<<BB * HH, THREADS, SM_TOTAL>>>(cpad, hpad, w, bb, (float*)d_out);
}

// round 17
// speedup vs baseline: 1.9996x; 1.4079x over previous
#include <cuda_runtime.h>
#include <cuda_bf16.h>
#include <cstdint>

#define BB 32
#define CC 5
#define HH 50
#define SS 20
#define EE 300
#define EPC 320              // padded K (zeros 300..319)
#define KK 20
#define F4N 75
#define NCS 100
#define THREADS 256
#define HG 5                 // h per block
#define NHG 10               // h-groups per b
#define NROWS_CDD (BB * CC * SS)     // 3200
#define NROWS_HIS (BB * HH * SS)     // 32000
#define NROWS_ALL (NROWS_CDD + NROWS_HIS)
#define NCHUNK 5             // K chunks of 64 bf16
#define ASTR 144             // smem row stride bytes (conflict-free ldmatrix)
#define SIMSTR 101           // sim row stride floats; only cols < NCS stored
#define NTASK (NCS * HG)     // 500

#define NC_STD  (-72.134752f)
#define NC_LAST (-721347.52f)

// smem offsets (bytes); sim overlays the staging region after last MMA
#define SM_AHI 0
#define SM_ALO (SM_AHI + 128 * ASTR)    // 18432
#define SM_BHI (SM_ALO + 128 * ASTR)    // 36864
#define SM_BLO (SM_BHI + 128 * ASTR)    // 55296
#define SM_SIM 0                        // overlay (128*101*4 = 51712 < 73728)
#define SM_PADH 73728                   // 100 floats
#define SM_WV   (SM_PADH + 400)         // 100 floats
#define SM_PADC (SM_WV + 400)           // 100 floats
#define SM_CONT (SM_PADC + 400)         // 500 floats
#define SM_FSC  (SM_CONT + 2048)        // 160 floats
#define SM_TOTAL (SM_FSC + 704)

static __device__ __forceinline__ uint32_t smem_u32(const void* p) {
    uint32_t a;
    asm("{ .reg .u64 t; cvta.to.shared.u64 t, %1; cvt.u32.u64 %0, t; }" : "=r"(a) : "l"(p));
    return a;
}
static __device__ __forceinline__ void ldsm_x4(uint32_t (&r)[4], uint32_t addr) {
    asm volatile("ldmatrix.sync.aligned.m8n8.x4.shared.b16 {%0,%1,%2,%3}, [%4];"
        : "=r"(r[0]), "=r"(r[1]), "=r"(r[2]), "=r"(r[3]) : "r"(addr));
}
static __device__ __forceinline__ void ldsm_x2(uint32_t (&r)[2], uint32_t addr) {
    asm volatile("ldmatrix.sync.aligned.m8n8.x2.shared.b16 {%0,%1}, [%2];"
        : "=r"(r[0]), "=r"(r[1]) : "r"(addr));
}
static __device__ __forceinline__ void mma16816(float (&d)[4], const uint32_t (&a)[4],
                                                const uint32_t (&b)[2]) {
    asm volatile("mma.sync.aligned.m16n8k16.row.col.f32.bf16.bf16.f32 "
        "{%0,%1,%2,%3}, {%4,%5,%6,%7}, {%8,%9}, {%0,%1,%2,%3};"
        : "+f"(d[0]), "+f"(d[1]), "+f"(d[2]), "+f"(d[3])
        : "r"(a[0]), "r"(a[1]), "r"(a[2]), "r"(a[3]), "r"(b[0]), "r"(b[1]));
}
__device__ __forceinline__ float ex2_approx(float x) {
    float r;
    asm("ex2.approx.ftz.f32 %0, %1;" : "=f"(r) : "f"(x));
    return r;
}

__device__ __align__(256) __nv_bfloat16 g_cddH[NROWS_CDD * EPC];
__device__ __align__(256) __nv_bfloat16 g_cddL[NROWS_CDD * EPC];
__device__ __align__(256) __nv_bfloat16 g_hisH[NROWS_HIS * EPC];
__device__ __align__(256) __nv_bfloat16 g_hisL[NROWS_HIS * EPC];
__device__ float g_partial[BB * HH * CC];
__device__ unsigned int g_done;

// ---------------- prep: normalize rows, split to bf16 hi/lo, pad K to 320 ----------------
__global__ __launch_bounds__(256)
void knrm_prep(const int* __restrict__ cand, const int* __restrict__ clk,
               const float* __restrict__ emb)
{
    const int wid = threadIdx.x >> 5, lane = threadIdx.x & 31;
    const int row = blockIdx.x * 8 + wid;
    if (row >= NROWS_ALL) return;
    const bool isCdd = (row < NROWS_CDD);
    int tok;
    __nv_bfloat16 *dH, *dL;
    if (isCdd) { tok = cand[row];
        dH = g_cddH + (size_t)row * EPC; dL = g_cddL + (size_t)row * EPC; }
    else { tok = clk[row - NROWS_CDD];
        dH = g_hisH + (size_t)(row - NROWS_CDD) * EPC; dL = g_hisL + (size_t)(row - NROWS_CDD) * EPC; }
    const float* src = emb + (size_t)tok * EE;

    float4 v[3];
    float ss = 0.f;
    #pragma unroll
    for (int i = 0; i < 3; ++i) {
        int f = lane + i * 32;
        if (f < F4N) {
            v[i] = *reinterpret_cast<const float4*>(src + f * 4);
            ss = fmaf(v[i].x, v[i].x, ss);
            ss = fmaf(v[i].y, v[i].y, ss);
            ss = fmaf(v[i].z, v[i].z, ss);
            ss = fmaf(v[i].w, v[i].w, ss);
        }
    }
    #pragma unroll
    for (int o = 16; o; o >>= 1) ss += __shfl_xor_sync(0xffffffffu, ss, o);
    float inv = 1.0f / fmaxf(sqrtf(ss), 1e-12f);
    #pragma unroll
    for (int i = 0; i < 3; ++i) {
        int f = lane + i * 32;
        if (f < EPC / 4) {
            float x0 = 0.f, x1 = 0.f, x2 = 0.f, x3 = 0.f;
            if (f < F4N) { x0 = v[i].x * inv; x1 = v[i].y * inv; x2 = v[i].z * inv; x3 = v[i].w * inv; }
            __nv_bfloat16 h0 = __float2bfloat16(x0), h1 = __float2bfloat16(x1);
            __nv_bfloat16 h2 = __float2bfloat16(x2), h3 = __float2bfloat16(x3);
            __nv_bfloat16 l0 = __float2bfloat16(x0 - __bfloat162float(h0));
            __nv_bfloat16 l1 = __float2bfloat16(x1 - __bfloat162float(h1));
            __nv_bfloat16 l2 = __float2bfloat16(x2 - __bfloat162float(h2));
            __nv_bfloat16 l3 = __float2bfloat16(x3 - __bfloat162float(h3));
            __nv_bfloat16 hp[4] = {h0, h1, h2, h3};
            __nv_bfloat16 lp[4] = {l0, l1, l2, l3};
            *reinterpret_cast<uint2*>(dH + f * 4) = *reinterpret_cast<uint2*>(hp);
            *reinterpret_cast<uint2*>(dL + f * 4) = *reinterpret_cast<uint2*>(lp);
        }
    }
}

// ---------------- main: 128x128x320 bf16 2-split GEMM (5 h per block) ----------------
__global__ __launch_bounds__(THREADS, 2)
void knrm_main(const float* __restrict__ cpad, const float* __restrict__ hpad,
               const float* __restrict__ ltr_w, const float* __restrict__ ltr_b,
               float* __restrict__ out)
{
    extern __shared__ char smem[];
    const uint32_t sb = smem_u32(smem);
    const int tid = threadIdx.x;
    const int wid = tid >> 5, lane = tid & 31;
    const int b = blockIdx.x / NHG;
    const int hg = blockIdx.x % NHG;

    float* simS  = reinterpret_cast<float*>(smem + SM_SIM);
    float* padhS = reinterpret_cast<float*>(smem + SM_PADH);
    float* wvS   = reinterpret_cast<float*>(smem + SM_WV);
    float* padcS = reinterpret_cast<float*>(smem + SM_PADC);
    float* contS = reinterpret_cast<float*>(smem + SM_CONT);
    float* fscS  = reinterpret_cast<float*>(smem + SM_FSC);

    if (tid < NCS) {
        padhS[tid] = hpad[(b * HH + hg * HG) * SS + tid];
        wvS[tid]   = ltr_w[(hg * HG) * KK + tid];
        padcS[tid] = cpad[b * NCS + tid];
    }

    const char* cH = reinterpret_cast<const char*>(g_cddH) + (size_t)b * NCS * EPC * 2;
    const char* cL = reinterpret_cast<const char*>(g_cddL) + (size_t)b * NCS * EPC * 2;
    const char* hHp = reinterpret_cast<const char*>(g_hisH) + (size_t)(b * HH + hg * HG) * SS * EPC * 2;
    const char* hLp = reinterpret_cast<const char*>(g_hisL) + (size_t)(b * HH + hg * HG) * SS * EPC * 2;

    const int m0 = (wid & 1) * 64;       // warp M base (4 m16 tiles)
    const int n0 = (wid >> 1) * 32;      // warp N base (4 n8 tiles)

    float d[4][4][4];
    #pragma unroll
    for (int mi = 0; mi < 4; ++mi)
        #pragma unroll
        for (int ni = 0; ni < 4; ++ni)
            #pragma unroll
            for (int q = 0; q < 4; ++q) d[mi][ni][q] = 0.f;

    const uint32_t aBaseH = sb + SM_AHI + (m0 + (lane & 15)) * ASTR + (lane >> 4) * 16;
    const uint32_t aBaseL = aBaseH + (SM_ALO - SM_AHI);
    const uint32_t bBaseH = sb + SM_BHI + (n0 + (lane & 7)) * ASTR + ((lane >> 3) & 1) * 16;
    const uint32_t bBaseL = bBaseH + (SM_BLO - SM_BHI);

    for (int c = 0; c < NCHUNK; ++c) {
        // stage A and B (128 rows each, rows >= 100 zeroed), both splits
        for (int i = tid; i < 128 * 8; i += THREADS) {
            int r = i >> 3, q = i & 7;
            uint32_t dst = r * ASTR + q * 16;
            uint4 zero = make_uint4(0, 0, 0, 0);
            if (r < NCS) {
                size_t src = (size_t)r * (EPC * 2) + c * 128 + q * 16;
                *reinterpret_cast<uint4*>(smem + SM_AHI + dst) = *reinterpret_cast<const uint4*>(cH + src);
                *reinterpret_cast<uint4*>(smem + SM_ALO + dst) = *reinterpret_cast<const uint4*>(cL + src);
                *reinterpret_cast<uint4*>(smem + SM_BHI + dst) = *reinterpret_cast<const uint4*>(hHp + src);
                *reinterpret_cast<uint4*>(smem + SM_BLO + dst) = *reinterpret_cast<const uint4*>(hLp + src);
            } else {
                *reinterpret_cast<uint4*>(smem + SM_AHI + dst) = zero;
                *reinterpret_cast<uint4*>(smem + SM_ALO + dst) = zero;
                *reinterpret_cast<uint4*>(smem + SM_BHI + dst) = zero;
                *reinterpret_cast<uint4*>(smem + SM_BLO + dst) = zero;
            }
        }
        __syncthreads();

        #pragma unroll
        for (int ks = 0; ks < 4; ++ks) {
            uint32_t bh[4][2], bl[4][2];
            #pragma unroll
            for (int ni = 0; ni < 4; ++ni) {
                ldsm_x2(bh[ni], bBaseH + ni * (8 * ASTR) + ks * 32);
                ldsm_x2(bl[ni], bBaseL + ni * (8 * ASTR) + ks * 32);
            }
            #pragma unroll
            for (int mi = 0; mi < 4; ++mi) {
                uint32_t ah[4], al[4];
                ldsm_x4(ah, aBaseH + mi * (16 * ASTR) + ks * 32);
                ldsm_x4(al, aBaseL + mi * (16 * ASTR) + ks * 32);
                #pragma unroll
                for (int ni = 0; ni < 4; ++ni) {
                    mma16816(d[mi][ni], ah, bh[ni]);
                    mma16816(d[mi][ni], ah, bl[ni]);
                    mma16816(d[mi][ni], al, bh[ni]);
                }
            }
        }
        __syncthreads();
    }

    // store sim (overlays staging; all ldsm reads completed at last barrier).
    // ONLY cols < NCS are stored: SIMSTR=101 < 128, pad cols would alias row+1.
    // col is even, so col < NCS implies col+1 <= 99 is also valid.
    #pragma unroll
    for (int mi = 0; mi < 4; ++mi)
        #pragma unroll
        for (int ni = 0; ni < 4; ++ni) {
            int row0 = m0 + mi * 16 + (lane >> 2);
            int col = n0 + ni * 8 + (lane & 3) * 2;
            if (col < NCS) {
                simS[row0 * SIMSTR + col]       = d[mi][ni][0];
                simS[row0 * SIMSTR + col + 1]   = d[mi][ni][1];
                simS[(row0 + 8) * SIMSTR + col]     = d[mi][ni][2];
                simS[(row0 + 8) * SIMSTR + col + 1] = d[mi][ni][3];
            }
        }
    __syncthreads();

    // phase B: task = hl*100 + cs; 500 tasks
    for (int task = tid; task < NTASK; task += THREADS) {
        int hl = task / NCS, cs = task - hl * NCS;
        float ps[KK];
        #pragma unroll
        for (int k = 0; k < KK; ++k) ps[k] = 0.f;
        #pragma unroll 4
        for (int t = 0; t < SS; ++t) {
            float s = simS[cs * SIMSTR + hl * SS + t];
            float pt = padhS[hl * SS + t];
            #pragma unroll
            for (int k = 0; k < KK; ++k) {
                float mu = -0.9f + 0.1f * (float)k;
                float nc = (k == 19) ? NC_LAST : NC_STD;
                float dd = s - mu;
                ps[k] = fmaf(pt, ex2_approx(dd * dd * nc), ps[k]);
            }
        }
        float accw = 0.f;
        #pragma unroll
        for (int k = 0; k < KK; ++k) {
            float lp = __logf(fmaxf(ps[k], 1e-10f));
            accw = fmaf(lp, wvS[hl * KK + k], accw);
        }
        contS[task] = accw * 0.01f * padcS[cs];
    }
    __syncthreads();

    // per (hl, c) reduction over s: 25 outputs
    if (tid < HG * CC) {
        int hl = tid / CC, c = tid % CC;
        float s = 0.f;
        #pragma unroll
        for (int i = 0; i < SS; ++i) s += contS[hl * NCS + c * SS + i];
        g_partial[(b * HH + hg * HG + hl) * CC + c] = s;
    }
    __syncthreads();

    // fused finalize
    __shared__ unsigned int isLast;
    if (tid == 0) {
        __threadfence();
        unsigned int v = atomicAdd(&g_done, 1u);
        isLast = (v == (unsigned)(BB * NHG - 1)) ? 1u : 0u;
    }
    __syncthreads();
    if (isLast) {
        if (tid == 0) { g_done = 0; __threadfence(); }
        for (int idx = tid; idx < BB * CC; idx += THREADS) {
            int bb2 = idx / CC, c = idx % CC;
            float s = ltr_b[0];
            for (int hh = 0; hh < HH; ++hh)
                s += g_partial[(bb2 * HH + hh) * CC + c];
            fscS[idx] = s;
        }
        __syncthreads();
        for (int idx = tid; idx < BB * CC; idx += THREADS) {
            int bb2 = idx / CC;
            float m = -1e30f;
            #pragma unroll
            for (int c2 = 0; c2 < CC; ++c2) m = fmaxf(m, fscS[bb2 * CC + c2]);
            float se = 0.f;
            #pragma unroll
            for (int c2 = 0; c2 < CC; ++c2) se += expf(fscS[bb2 * CC + c2] - m);
            out[idx] = fscS[idx] - m - logf(se);
        }
    }
}

extern "C" void kernel_launch(void* const* d_in, const int* in_sizes, int n_in,
                              void* d_out, int out_size)
{
    const int*   cand = (const int*)  d_in[0];
    const int*   clk  = (const int*)  d_in[1];
    const float* cpad = (const float*)d_in[2];
    const float* hpad = (const float*)d_in[3];
    const float* emb  = (const float*)d_in[4];
    const float* w    = (const float*)d_in[5];
    const float* bb   = (const float*)d_in[6];

    cudaFuncSetAttribute(knrm_main, cudaFuncAttributeMaxDynamicSharedMemorySize, SM_TOTAL);

    knrm_prep<<<(NROWS_ALL + 7) / 8, 256>>>(cand, clk, emb);
    knrm_main<<<BB * NHG, THREADS, SM_TOTAL>>>(cpad, hpad, w, bb, (float*)d_out);
}